// round 13
// baseline (speedup 1.0000x reference)
#include <cuda_runtime.h>
#include <cuda_fp16.h>
#include <math.h>
#include <stdint.h>

#define HID     256
#define PTS     16                // points per CTA (2 n8 mma tiles)
#define THREADS 256               // 8 warps
#define NJJ     2                 // j-tiles (m16) per warp: 8 warps * 2 * 16 = 256 outputs
#define NT      2                 // n8 tiles
#define NCH     5                 // value, d0, d1, d2, laplacian
#define CHB     528               // bytes per (ks,ch,nt) fragment block (512 + 16 pad)
#define FRAG_OFF(ks,ch,nt) ((((ks)*NCH+(ch))*2+(nt))*CHB)
#define OFF_RED (16 * NCH * 2 * CHB)   // 84480
#define OFF_INP (OFF_RED + 128)
#define SMEM_ALLOC (OFF_INP + 192)

__device__ double g_acc;
// fp16 hi-split A-fragment images: [layer][jt][ks][lane] -> uint4 (a0..a3)
__device__ uint4 g_aimg[2 * 16 * 16 * 32];

static __device__ __forceinline__ int aidx(int layer, int jt, int ks, int lane) {
    return (((layer * 16 + jt) * 16 + ks) * 32) + lane;
}

__device__ __forceinline__ void mma_f16(float* d, const uint32_t* a, const uint32_t* b) {
    asm volatile(
        "mma.sync.aligned.m16n8k16.row.col.f32.f16.f16.f32 "
        "{%0,%1,%2,%3},{%4,%5,%6,%7},{%8,%9},{%0,%1,%2,%3};"
        : "+f"(d[0]), "+f"(d[1]), "+f"(d[2]), "+f"(d[3])
        : "r"(a[0]), "r"(a[1]), "r"(a[2]), "r"(a[3]), "r"(b[0]), "r"(b[1]));
}

// tanh via ex2.approx + rcp.approx: rel err ~1e-6, ~5 instrs vs ~20 for tanhf.
// tanh(z) = 1 - 2/(exp(2z)+1); exp(2z) = 2^(z * 2*log2(e)).
__device__ __forceinline__ float fast_tanh(float z) {
    float e;
    asm("ex2.approx.f32 %0, %1;" : "=f"(e) : "f"(z * 2.8853900817779268f));
    float r;
    asm("rcp.approx.f32 %0, %1;" : "=f"(r) : "f"(e + 1.0f));
    return fmaf(-2.0f, r, 1.0f);
}

// fp16 hi/lo split of activation v at (point p, next-layer input dim j),
// written directly in mma B-fragment order.
__device__ __forceinline__ void frag_store(char* act, int ch, int p, int j, float v) {
    int ks = j >> 4, j16 = j & 15;
    int tk = (j16 >> 1) & 3, b1 = j16 >> 3, b0 = j16 & 1;
    int nt = p >> 3, p8 = p & 7;
    char* base = act + FRAG_OFF(ks, ch, nt) + (p8 * 4 + tk) * 16 + b1 * 4 + b0 * 2;
    __half hi = __float2half_rn(v);
    __half lo = __float2half_rn(v - __half2float(hi));
    *(unsigned short*)base       = *(unsigned short*)&hi;
    *(unsigned short*)(base + 8) = *(unsigned short*)&lo;
}

// ============ prep: W2/W3 -> fp16 hi mma A-fragment images ============
__global__ void prep_kernel(const float* __restrict__ W2, const float* __restrict__ W3) {
    int e = blockIdx.x * blockDim.x + threadIdx.x;
    if (e >= 2 * 16 * 16 * 32) return;
    int lane = e & 31, ks = (e >> 5) & 15, jt = (e >> 9) & 15, layer = (e >> 13) & 1;
    const float* W = layer ? W3 : W2;
    int gid = lane >> 2, tig = lane & 3;
    uint32_t regs[4];
#pragma unroll
    for (int r = 0; r < 4; r++) {
        int j = jt * 16 + gid + ((r & 1) << 3);
        int k = ks * 16 + tig * 2 + ((r >> 1) << 3);
        __half h0 = __float2half_rn(W[k * HID + j]);
        __half h1 = __float2half_rn(W[(k + 1) * HID + j]);
        regs[r] = (uint32_t)*(unsigned short*)&h0 | ((uint32_t)*(unsigned short*)&h1 << 16);
    }
    g_aimg[e] = make_uint4(regs[0], regs[1], regs[2], regs[3]);
}

// ============ main kernel ============
__global__ void __launch_bounds__(THREADS, 2) helm_hmma(
    const float* __restrict__ inputs,
    const float* __restrict__ W1, const float* __restrict__ b1,
    const float* __restrict__ b2, const float* __restrict__ b3,
    const float* __restrict__ W4, const float* __restrict__ b4,
    int n, float k2) {

    extern __shared__ char act[];
    float* red = (float*)(act + OFF_RED);   // [16] u, [16] l
    float* inp = (float*)(act + OFF_INP);   // [16][3]

    int tid = threadIdx.x, wid = tid >> 5, lane = tid & 31;
    int gid = lane >> 2, tig = lane & 3;
    int pt0 = blockIdx.x * PTS;

    if (tid < 32) red[tid] = 0.f;
    if (tid < PTS * 3) {
        int p = tid / 3, c = tid % 3;
        inp[tid] = (pt0 + p < n) ? inputs[(pt0 + p) * 3 + c] : 0.f;
    }
    __syncthreads();

    // ---- Layer 1 (3 -> 256): thread = output unit j ----
    {
        int j = tid;
        float w0 = W1[j], w1 = W1[HID + j], w2 = W1[2 * HID + j], bb = b1[j];
        float wss = w0 * w0 + w1 * w1 + w2 * w2;
#pragma unroll
        for (int p = 0; p < PTS; p++) {
            float x0 = inp[p * 3 + 0], x1 = inp[p * 3 + 1], x2 = inp[p * 3 + 2];
            float z = fmaf(x0, w0, fmaf(x1, w1, fmaf(x2, w2, bb)));
            float y = fast_tanh(z);
            float g = 1.f - y * y;
            float tg = 2.f * y * g;
            frag_store(act, 0, p, j, y);
            frag_store(act, 1, p, j, g * w0);
            frag_store(act, 2, p, j, g * w1);
            frag_store(act, 3, p, j, g * w2);
            frag_store(act, 4, p, j, -tg * wss);       // laplacian channel
        }
    }
    __syncthreads();

    float acc[NCH][NJJ][NT][4];
    float us[NT][2], ls[NT][2];
#pragma unroll
    for (int nt = 0; nt < NT; nt++)
#pragma unroll
        for (int b0 = 0; b0 < 2; b0++) { us[nt][b0] = 0.f; ls[nt][b0] = 0.f; }

    for (int layer = 0; layer < 2; layer++) {
#pragma unroll
        for (int c = 0; c < NCH; c++)
#pragma unroll
            for (int jj = 0; jj < NJJ; jj++)
#pragma unroll
                for (int nt = 0; nt < NT; nt++)
#pragma unroll
                    for (int r = 0; r < 4; r++) acc[c][jj][nt][r] = 0.f;

        // ---- GEMM: 2-pass fp16 (ah*bh + ah*bl), A prefetch pipelined ----
        uint4 ah[NJJ], ahn[NJJ];
#pragma unroll
        for (int jj = 0; jj < NJJ; jj++)
            ah[jj] = g_aimg[aidx(layer, wid * NJJ + jj, 0, lane)];
        for (int ks = 0; ks < 16; ks++) {
            int ksn = (ks < 15) ? ks + 1 : 15;
#pragma unroll
            for (int jj = 0; jj < NJJ; jj++)
                ahn[jj] = g_aimg[aidx(layer, wid * NJJ + jj, ksn, lane)];
#pragma unroll
            for (int ch = 0; ch < NCH; ch++)
#pragma unroll
                for (int nt = 0; nt < NT; nt++) {
                    uint4 bf = *(const uint4*)(act + FRAG_OFF(ks, ch, nt) + lane * 16);
                    uint32_t bh[2] = {bf.x, bf.y}, bl[2] = {bf.z, bf.w};
#pragma unroll
                    for (int jj = 0; jj < NJJ; jj++) {
                        mma_f16(acc[ch][jj][nt], (const uint32_t*)&ah[jj], bh);
                        mma_f16(acc[ch][jj][nt], (const uint32_t*)&ah[jj], bl);
                    }
                }
#pragma unroll
            for (int jj = 0; jj < NJJ; jj++) ah[jj] = ahn[jj];
        }
        __syncthreads();   // all fragment reads done before act is overwritten

        if (layer == 0) {
#pragma unroll
            for (int jj = 0; jj < NJJ; jj++)
#pragma unroll
                for (int nt = 0; nt < NT; nt++)
#pragma unroll
                    for (int r = 0; r < 4; r++) {
                        int j = (wid * NJJ + jj) * 16 + gid + ((r >> 1) << 3);
                        int p = nt * 8 + tig * 2 + (r & 1);
                        float zv = acc[0][jj][nt][r] + b2[j];
                        float y = fast_tanh(zv);
                        float g = 1.f - y * y;
                        float tg = 2.f * y * g;
                        float zd0 = acc[1][jj][nt][r];
                        float zd1 = acc[2][jj][nt][r];
                        float zd2 = acc[3][jj][nt][r];
                        float zl  = acc[4][jj][nt][r];
                        frag_store(act, 0, p, j, y);
                        frag_store(act, 1, p, j, g * zd0);
                        frag_store(act, 2, p, j, g * zd1);
                        frag_store(act, 3, p, j, g * zd2);
                        float dsq = fmaf(zd0, zd0, fmaf(zd1, zd1, zd2 * zd2));
                        frag_store(act, 4, p, j, fmaf(g, zl, -tg * dsq));
                    }
            __syncthreads();
        } else {
#pragma unroll
            for (int jj = 0; jj < NJJ; jj++)
#pragma unroll
                for (int nt = 0; nt < NT; nt++)
#pragma unroll
                    for (int r = 0; r < 4; r++) {
                        int j = (wid * NJJ + jj) * 16 + gid + ((r >> 1) << 3);
                        float w4 = W4[j];
                        float zv = acc[0][jj][nt][r] + b3[j];
                        float y = fast_tanh(zv);
                        float g = 1.f - y * y;
                        float tg = 2.f * y * g;
                        float zd0 = acc[1][jj][nt][r];
                        float zd1 = acc[2][jj][nt][r];
                        float zd2 = acc[3][jj][nt][r];
                        float zl  = acc[4][jj][nt][r];
                        float dsq = fmaf(zd0, zd0, fmaf(zd1, zd1, zd2 * zd2));
                        float lap = fmaf(g, zl, -tg * dsq);
                        us[nt][r & 1] = fmaf(y, w4, us[nt][r & 1]);
                        ls[nt][r & 1] = fmaf(lap, w4, ls[nt][r & 1]);
                    }
        }
    }

    // reduce over gid (lane bits 2..4); survivors lanes 0..3 (tig)
#pragma unroll
    for (int off = 4; off <= 16; off <<= 1)
#pragma unroll
        for (int nt = 0; nt < NT; nt++)
#pragma unroll
            for (int b0 = 0; b0 < 2; b0++) {
                us[nt][b0] += __shfl_xor_sync(0xFFFFFFFFu, us[nt][b0], off);
                ls[nt][b0] += __shfl_xor_sync(0xFFFFFFFFu, ls[nt][b0], off);
            }
    if (gid == 0) {
#pragma unroll
        for (int nt = 0; nt < NT; nt++)
#pragma unroll
            for (int b0 = 0; b0 < 2; b0++) {
                int p = nt * 8 + tig * 2 + b0;
                atomicAdd(&red[p], us[nt][b0]);
                atomicAdd(&red[16 + p], ls[nt][b0]);
            }
    }

    __syncthreads();
    if (wid == 0) {
        float rr = 0.f;
        if (lane < PTS && pt0 + lane < n) {
            float u = red[lane] + b4[0];
            float l = red[16 + lane];
            float r = l + k2 * u;
            rr = r * r;
        }
#pragma unroll
        for (int off = 16; off > 0; off >>= 1)
            rr += __shfl_xor_sync(0xFFFFFFFFu, rr, off);
        if (lane == 0) atomicAdd(&g_acc, (double)rr);
    }
}

__global__ void k_zero() { g_acc = 0.0; }
__global__ void k_fin(float* out, double inv_n) { out[0] = (float)(g_acc * inv_n); }

extern "C" void kernel_launch(void* const* d_in, const int* in_sizes, int n_in,
                              void* d_out, int out_size) {
    const float* inputs = (const float*)d_in[0];
    const float* W1 = (const float*)d_in[1];
    const float* b1 = (const float*)d_in[2];
    const float* W2 = (const float*)d_in[3];
    const float* b2 = (const float*)d_in[4];
    const float* W3 = (const float*)d_in[5];
    const float* b3 = (const float*)d_in[6];
    const float* W4 = (const float*)d_in[7];
    const float* b4 = (const float*)d_in[8];

    int n = in_sizes[0] / 3;
    const double C = 343.0;
    const double OMEGA = 2.0 * 3.14159265358979323846 * 1000.0;
    float k2 = (float)((C / OMEGA) * (C / OMEGA));

    cudaFuncSetAttribute(helm_hmma, cudaFuncAttributeMaxDynamicSharedMemorySize, SMEM_ALLOC);

    int blocks = (n + PTS - 1) / PTS;
    k_zero<<<1, 1>>>();
    prep_kernel<<<(2 * 16 * 16 * 32 + 255) / 256, 256>>>(W2, W3);
    helm_hmma<<<blocks, THREADS, SMEM_ALLOC>>>(inputs, W1, b1, b2, b3, W4, b4, n, k2);
    k_fin<<<1, 1>>>((float*)d_out, 1.0 / (double)n);
}

// round 16
// speedup vs baseline: 1.8045x; 1.8045x over previous
#include <cuda_runtime.h>
#include <cuda_fp16.h>
#include <math.h>
#include <stdint.h>

#define HID     256
#define PTS     16                // points per CTA (2 n8 mma tiles)
#define THREADS 128               // 4 warps
#define NJJ     4                 // j-tiles (m16) per warp: 4 warps * 4 * 16 = 256 outputs
#define NT      2                 // n8 tiles
#define NCH     5                 // value, d0, d1, d2, laplacian
#define CHB     272               // bytes per (ks,ch,nt) fragment block (256 + 16 pad)
#define FRAG_OFF(ks,ch,nt) ((((ks)*NCH+(ch))*2+(nt))*CHB)
#define OFF_RED (16 * NCH * 2 * CHB)   // 43520
#define OFF_INP (OFF_RED + 128)
#define SMEM_ALLOC (OFF_INP + 192)

__device__ double g_acc;
// fp16 A-fragment images: [layer][jt][ks][lane] -> uint4 (a0..a3)
__device__ uint4 g_aimg[2 * 16 * 16 * 32];

static __device__ __forceinline__ int aidx(int layer, int jt, int ks, int lane) {
    return (((layer * 16 + jt) * 16 + ks) * 32) + lane;
}

__device__ __forceinline__ void mma_f16(float* d, const uint32_t* a, const uint32_t* b) {
    asm volatile(
        "mma.sync.aligned.m16n8k16.row.col.f32.f16.f16.f32 "
        "{%0,%1,%2,%3},{%4,%5,%6,%7},{%8,%9},{%0,%1,%2,%3};"
        : "+f"(d[0]), "+f"(d[1]), "+f"(d[2]), "+f"(d[3])
        : "r"(a[0]), "r"(a[1]), "r"(a[2]), "r"(a[3]), "r"(b[0]), "r"(b[1]));
}

// tanh via ex2.approx + rcp.approx: abs err ~1e-6, ~5 instrs vs ~20 for tanhf.
__device__ __forceinline__ float fast_tanh(float z) {
    float e;
    asm("ex2.approx.f32 %0, %1;" : "=f"(e) : "f"(z * 2.8853900817779268f));
    float r;
    asm("rcp.approx.f32 %0, %1;" : "=f"(r) : "f"(e + 1.0f));
    return fmaf(-2.0f, r, 1.0f);
}

// fp16 activation v at (point p, next-layer input dim j), written directly
// in mma B-fragment order (hi only, single-pass GEMM).
__device__ __forceinline__ void frag_store(char* act, int ch, int p, int j, float v) {
    int ks = j >> 4, j16 = j & 15;
    int tk = (j16 >> 1) & 3, b1 = j16 >> 3, b0 = j16 & 1;
    int nt = p >> 3, p8 = p & 7;
    char* base = act + FRAG_OFF(ks, ch, nt) + (p8 * 4 + tk) * 8 + b1 * 4 + b0 * 2;
    __half hi = __float2half_rn(v);
    *(unsigned short*)base = *(unsigned short*)&hi;
}

// ============ prep: W2/W3 -> fp16 mma A-fragment images ============
__global__ void prep_kernel(const float* __restrict__ W2, const float* __restrict__ W3) {
    int e = blockIdx.x * blockDim.x + threadIdx.x;
    if (e >= 2 * 16 * 16 * 32) return;
    int lane = e & 31, ks = (e >> 5) & 15, jt = (e >> 9) & 15, layer = (e >> 13) & 1;
    const float* W = layer ? W3 : W2;
    int gid = lane >> 2, tig = lane & 3;
    uint32_t regs[4];
#pragma unroll
    for (int r = 0; r < 4; r++) {
        int j = jt * 16 + gid + ((r & 1) << 3);
        int k = ks * 16 + tig * 2 + ((r >> 1) << 3);
        __half h0 = __float2half_rn(W[k * HID + j]);
        __half h1 = __float2half_rn(W[(k + 1) * HID + j]);
        regs[r] = (uint32_t)*(unsigned short*)&h0 | ((uint32_t)*(unsigned short*)&h1 << 16);
    }
    g_aimg[e] = make_uint4(regs[0], regs[1], regs[2], regs[3]);
}

// ============ main kernel ============
__global__ void __launch_bounds__(THREADS, 2) helm_hmma(
    const float* __restrict__ inputs,
    const float* __restrict__ W1, const float* __restrict__ b1,
    const float* __restrict__ b2, const float* __restrict__ b3,
    const float* __restrict__ W4, const float* __restrict__ b4,
    int n, float k2) {

    extern __shared__ char act[];
    float* red = (float*)(act + OFF_RED);   // [16] u, [16] l
    float* inp = (float*)(act + OFF_INP);   // [16][3]

    int tid = threadIdx.x, wid = tid >> 5, lane = tid & 31;
    int gid = lane >> 2, tig = lane & 3;
    int pt0 = blockIdx.x * PTS;

    if (tid < 32) red[tid] = 0.f;
    if (tid < PTS * 3) {
        int p = tid / 3, c = tid % 3;
        inp[tid] = (pt0 + p < n) ? inputs[(pt0 + p) * 3 + c] : 0.f;
    }
    __syncthreads();

    // ---- Layer 1 (3 -> 256): thread handles j = tid and tid+128 ----
#pragma unroll
    for (int jh = 0; jh < 2; jh++) {
        int j = tid + jh * 128;
        float w0 = W1[j], w1 = W1[HID + j], w2 = W1[2 * HID + j], bb = b1[j];
        float wss = w0 * w0 + w1 * w1 + w2 * w2;
#pragma unroll
        for (int p = 0; p < PTS; p++) {
            float x0 = inp[p * 3 + 0], x1 = inp[p * 3 + 1], x2 = inp[p * 3 + 2];
            float z = fmaf(x0, w0, fmaf(x1, w1, fmaf(x2, w2, bb)));
            float y = fast_tanh(z);
            float g = 1.f - y * y;
            float tg = 2.f * y * g;
            frag_store(act, 0, p, j, y);
            frag_store(act, 1, p, j, g * w0);
            frag_store(act, 2, p, j, g * w1);
            frag_store(act, 3, p, j, g * w2);
            frag_store(act, 4, p, j, -tg * wss);       // laplacian channel
        }
    }
    __syncthreads();

    float acc[NCH][NJJ][NT][4];
    float us[NT][2], ls[NT][2];
#pragma unroll
    for (int nt = 0; nt < NT; nt++)
#pragma unroll
        for (int b0 = 0; b0 < 2; b0++) { us[nt][b0] = 0.f; ls[nt][b0] = 0.f; }

    for (int layer = 0; layer < 2; layer++) {
#pragma unroll
        for (int c = 0; c < NCH; c++)
#pragma unroll
            for (int jj = 0; jj < NJJ; jj++)
#pragma unroll
                for (int nt = 0; nt < NT; nt++)
#pragma unroll
                    for (int r = 0; r < 4; r++) acc[c][jj][nt][r] = 0.f;

        // ---- GEMM: single-pass fp16, A prefetch pipelined ----
        uint4 ah[NJJ], ahn[NJJ];
#pragma unroll
        for (int jj = 0; jj < NJJ; jj++)
            ah[jj] = g_aimg[aidx(layer, wid * NJJ + jj, 0, lane)];
        for (int ks = 0; ks < 16; ks++) {
            int ksn = (ks < 15) ? ks + 1 : 15;
#pragma unroll
            for (int jj = 0; jj < NJJ; jj++)
                ahn[jj] = g_aimg[aidx(layer, wid * NJJ + jj, ksn, lane)];
#pragma unroll
            for (int ch = 0; ch < NCH; ch++)
#pragma unroll
                for (int nt = 0; nt < NT; nt++) {
                    uint2 bf = *(const uint2*)(act + FRAG_OFF(ks, ch, nt) + lane * 8);
                    uint32_t bh[2] = {bf.x, bf.y};
#pragma unroll
                    for (int jj = 0; jj < NJJ; jj++)
                        mma_f16(acc[ch][jj][nt], (const uint32_t*)&ah[jj], bh);
                }
#pragma unroll
            for (int jj = 0; jj < NJJ; jj++) ah[jj] = ahn[jj];
        }
        __syncthreads();   // all fragment reads done before act is overwritten

        if (layer == 0) {
#pragma unroll
            for (int jj = 0; jj < NJJ; jj++)
#pragma unroll
                for (int nt = 0; nt < NT; nt++)
#pragma unroll
                    for (int r = 0; r < 4; r++) {
                        int j = (wid * NJJ + jj) * 16 + gid + ((r >> 1) << 3);
                        int p = nt * 8 + tig * 2 + (r & 1);
                        float zv = acc[0][jj][nt][r] + b2[j];
                        float y = fast_tanh(zv);
                        float g = 1.f - y * y;
                        float tg = 2.f * y * g;
                        float zd0 = acc[1][jj][nt][r];
                        float zd1 = acc[2][jj][nt][r];
                        float zd2 = acc[3][jj][nt][r];
                        float zl  = acc[4][jj][nt][r];
                        frag_store(act, 0, p, j, y);
                        frag_store(act, 1, p, j, g * zd0);
                        frag_store(act, 2, p, j, g * zd1);
                        frag_store(act, 3, p, j, g * zd2);
                        float dsq = fmaf(zd0, zd0, fmaf(zd1, zd1, zd2 * zd2));
                        frag_store(act, 4, p, j, fmaf(g, zl, -tg * dsq));
                    }
            __syncthreads();
        } else {
#pragma unroll
            for (int jj = 0; jj < NJJ; jj++)
#pragma unroll
                for (int nt = 0; nt < NT; nt++)
#pragma unroll
                    for (int r = 0; r < 4; r++) {
                        int j = (wid * NJJ + jj) * 16 + gid + ((r >> 1) << 3);
                        float w4 = W4[j];
                        float zv = acc[0][jj][nt][r] + b3[j];
                        float y = fast_tanh(zv);
                        float g = 1.f - y * y;
                        float tg = 2.f * y * g;
                        float zd0 = acc[1][jj][nt][r];
                        float zd1 = acc[2][jj][nt][r];
                        float zd2 = acc[3][jj][nt][r];
                        float zl  = acc[4][jj][nt][r];
                        float dsq = fmaf(zd0, zd0, fmaf(zd1, zd1, zd2 * zd2));
                        float lap = fmaf(g, zl, -tg * dsq);
                        us[nt][r & 1] = fmaf(y, w4, us[nt][r & 1]);
                        ls[nt][r & 1] = fmaf(lap, w4, ls[nt][r & 1]);
                    }
        }
    }

    // reduce over gid (lane bits 2..4); survivors lanes 0..3 (tig)
#pragma unroll
    for (int off = 4; off <= 16; off <<= 1)
#pragma unroll
        for (int nt = 0; nt < NT; nt++)
#pragma unroll
            for (int b0 = 0; b0 < 2; b0++) {
                us[nt][b0] += __shfl_xor_sync(0xFFFFFFFFu, us[nt][b0], off);
                ls[nt][b0] += __shfl_xor_sync(0xFFFFFFFFu, ls[nt][b0], off);
            }
    if (gid == 0) {
#pragma unroll
        for (int nt = 0; nt < NT; nt++)
#pragma unroll
            for (int b0 = 0; b0 < 2; b0++) {
                int p = nt * 8 + tig * 2 + b0;
                atomicAdd(&red[p], us[nt][b0]);
                atomicAdd(&red[16 + p], ls[nt][b0]);
            }
    }

    __syncthreads();
    if (wid == 0) {
        float rr = 0.f;
        if (lane < PTS && pt0 + lane < n) {
            float u = red[lane] + b4[0];
            float l = red[16 + lane];
            float r = l + k2 * u;
            rr = r * r;
        }
#pragma unroll
        for (int off = 16; off > 0; off >>= 1)
            rr += __shfl_xor_sync(0xFFFFFFFFu, rr, off);
        if (lane == 0) atomicAdd(&g_acc, (double)rr);
    }
}

__global__ void k_zero() { g_acc = 0.0; }
__global__ void k_fin(float* out, double inv_n) { out[0] = (float)(g_acc * inv_n); }

extern "C" void kernel_launch(void* const* d_in, const int* in_sizes, int n_in,
                              void* d_out, int out_size) {
    const float* inputs = (const float*)d_in[0];
    const float* W1 = (const float*)d_in[1];
    const float* b1 = (const float*)d_in[2];
    const float* W2 = (const float*)d_in[3];
    const float* b2 = (const float*)d_in[4];
    const float* W3 = (const float*)d_in[5];
    const float* b3 = (const float*)d_in[6];
    const float* W4 = (const float*)d_in[7];
    const float* b4 = (const float*)d_in[8];

    int n = in_sizes[0] / 3;
    const double C = 343.0;
    const double OMEGA = 2.0 * 3.14159265358979323846 * 1000.0;
    float k2 = (float)((C / OMEGA) * (C / OMEGA));

    cudaFuncSetAttribute(helm_hmma, cudaFuncAttributeMaxDynamicSharedMemorySize, SMEM_ALLOC);

    int blocks = (n + PTS - 1) / PTS;
    k_zero<<<1, 1>>>();
    prep_kernel<<<(2 * 16 * 16 * 32 + 255) / 256, 256>>>(W2, W3);
    helm_hmma<<<blocks, THREADS, SMEM_ALLOC>>>(inputs, W1, b1, b2, b3, W4, b4, n, k2);
    k_fin<<<1, 1>>>((float*)d_out, 1.0 / (double)n);
}

// round 17
// speedup vs baseline: 1.8432x; 1.0214x over previous
#include <cuda_runtime.h>
#include <cuda_fp16.h>
#include <math.h>
#include <stdint.h>

#define HID     256
#define PTS     16                // points per CTA (2 n8 mma tiles)
#define THREADS 256               // 8 warps
#define NJJ     2                 // j-tiles (m16) per warp: 8 warps * 2 * 16 = 256 outputs
#define NT      2                 // n8 tiles
#define NCH     5                 // value, d0, d1, d2, laplacian
#define CHB     272               // bytes per (ks,ch,nt) fragment block (256 + 16 pad)
#define FRAG_OFF(ks,ch,nt) ((((ks)*NCH+(ch))*2+(nt))*CHB)
#define OFF_RED (16 * NCH * 2 * CHB)   // 43520
#define OFF_INP (OFF_RED + 128)
#define SMEM_ALLOC (OFF_INP + 192)

__device__ double g_acc;
// fp16 A-fragment images: [layer][jt][ks][lane] -> uint4 (a0..a3)
__device__ uint4 g_aimg[2 * 16 * 16 * 32];

static __device__ __forceinline__ int aidx(int layer, int jt, int ks, int lane) {
    return (((layer * 16 + jt) * 16 + ks) * 32) + lane;
}

__device__ __forceinline__ void mma_f16(float* d, const uint32_t* a, const uint32_t* b) {
    asm volatile(
        "mma.sync.aligned.m16n8k16.row.col.f32.f16.f16.f32 "
        "{%0,%1,%2,%3},{%4,%5,%6,%7},{%8,%9},{%0,%1,%2,%3};"
        : "+f"(d[0]), "+f"(d[1]), "+f"(d[2]), "+f"(d[3])
        : "r"(a[0]), "r"(a[1]), "r"(a[2]), "r"(a[3]), "r"(b[0]), "r"(b[1]));
}

// tanh via ex2.approx + rcp.approx: abs err ~1e-6, ~5 instrs vs ~20 for tanhf.
__device__ __forceinline__ float fast_tanh(float z) {
    float e;
    asm("ex2.approx.f32 %0, %1;" : "=f"(e) : "f"(z * 2.8853900817779268f));
    float r;
    asm("rcp.approx.f32 %0, %1;" : "=f"(r) : "f"(e + 1.0f));
    return fmaf(-2.0f, r, 1.0f);
}

// fp16 activation v at (point p, next-layer input dim j), written directly
// in mma B-fragment order (hi only, single-pass GEMM).
__device__ __forceinline__ void frag_store(char* act, int ch, int p, int j, float v) {
    int ks = j >> 4, j16 = j & 15;
    int tk = (j16 >> 1) & 3, b1 = j16 >> 3, b0 = j16 & 1;
    int nt = p >> 3, p8 = p & 7;
    char* base = act + FRAG_OFF(ks, ch, nt) + (p8 * 4 + tk) * 8 + b1 * 4 + b0 * 2;
    __half hi = __float2half_rn(v);
    *(unsigned short*)base = *(unsigned short*)&hi;
}

// ============ prep: W2/W3 -> fp16 mma A-fragment images ============
__global__ void prep_kernel(const float* __restrict__ W2, const float* __restrict__ W3) {
    int e = blockIdx.x * blockDim.x + threadIdx.x;
    if (e >= 2 * 16 * 16 * 32) return;
    int lane = e & 31, ks = (e >> 5) & 15, jt = (e >> 9) & 15, layer = (e >> 13) & 1;
    const float* W = layer ? W3 : W2;
    int gid = lane >> 2, tig = lane & 3;
    uint32_t regs[4];
#pragma unroll
    for (int r = 0; r < 4; r++) {
        int j = jt * 16 + gid + ((r & 1) << 3);
        int k = ks * 16 + tig * 2 + ((r >> 1) << 3);
        __half h0 = __float2half_rn(W[k * HID + j]);
        __half h1 = __float2half_rn(W[(k + 1) * HID + j]);
        regs[r] = (uint32_t)*(unsigned short*)&h0 | ((uint32_t)*(unsigned short*)&h1 << 16);
    }
    g_aimg[e] = make_uint4(regs[0], regs[1], regs[2], regs[3]);
}

// ============ main kernel ============
__global__ void __launch_bounds__(THREADS, 2) helm_hmma(
    const float* __restrict__ inputs,
    const float* __restrict__ W1, const float* __restrict__ b1,
    const float* __restrict__ b2, const float* __restrict__ b3,
    const float* __restrict__ W4, const float* __restrict__ b4,
    int n, float k2) {

    extern __shared__ char act[];
    float* red = (float*)(act + OFF_RED);   // [16] u, [16] l
    float* inp = (float*)(act + OFF_INP);   // [16][3]

    int tid = threadIdx.x, wid = tid >> 5, lane = tid & 31;
    int gid = lane >> 2, tig = lane & 3;
    int pt0 = blockIdx.x * PTS;

    if (tid < 32) red[tid] = 0.f;
    if (tid < PTS * 3) {
        int p = tid / 3, c = tid % 3;
        inp[tid] = (pt0 + p < n) ? inputs[(pt0 + p) * 3 + c] : 0.f;
    }
    __syncthreads();

    // ---- Layer 1 (3 -> 256): thread = output unit j ----
    {
        int j = tid;
        float w0 = W1[j], w1 = W1[HID + j], w2 = W1[2 * HID + j], bb = b1[j];
        float wss = w0 * w0 + w1 * w1 + w2 * w2;
#pragma unroll
        for (int p = 0; p < PTS; p++) {
            float x0 = inp[p * 3 + 0], x1 = inp[p * 3 + 1], x2 = inp[p * 3 + 2];
            float z = fmaf(x0, w0, fmaf(x1, w1, fmaf(x2, w2, bb)));
            float y = fast_tanh(z);
            float g = 1.f - y * y;
            float tg = 2.f * y * g;
            frag_store(act, 0, p, j, y);
            frag_store(act, 1, p, j, g * w0);
            frag_store(act, 2, p, j, g * w1);
            frag_store(act, 3, p, j, g * w2);
            frag_store(act, 4, p, j, -tg * wss);       // laplacian channel
        }
    }
    __syncthreads();

    float acc[NCH][NJJ][NT][4];
    float us[NT][2], ls[NT][2];
#pragma unroll
    for (int nt = 0; nt < NT; nt++)
#pragma unroll
        for (int b0 = 0; b0 < 2; b0++) { us[nt][b0] = 0.f; ls[nt][b0] = 0.f; }

    for (int layer = 0; layer < 2; layer++) {
#pragma unroll
        for (int c = 0; c < NCH; c++)
#pragma unroll
            for (int jj = 0; jj < NJJ; jj++)
#pragma unroll
                for (int nt = 0; nt < NT; nt++)
#pragma unroll
                    for (int r = 0; r < 4; r++) acc[c][jj][nt][r] = 0.f;

        // ---- GEMM: single-pass fp16, A prefetch pipelined ----
        uint4 ah[NJJ], ahn[NJJ];
#pragma unroll
        for (int jj = 0; jj < NJJ; jj++)
            ah[jj] = g_aimg[aidx(layer, wid * NJJ + jj, 0, lane)];
        for (int ks = 0; ks < 16; ks++) {
            int ksn = (ks < 15) ? ks + 1 : 15;
#pragma unroll
            for (int jj = 0; jj < NJJ; jj++)
                ahn[jj] = g_aimg[aidx(layer, wid * NJJ + jj, ksn, lane)];
#pragma unroll
            for (int ch = 0; ch < NCH; ch++)
#pragma unroll
                for (int nt = 0; nt < NT; nt++) {
                    uint2 bf = *(const uint2*)(act + FRAG_OFF(ks, ch, nt) + lane * 8);
                    uint32_t bh[2] = {bf.x, bf.y};
#pragma unroll
                    for (int jj = 0; jj < NJJ; jj++)
                        mma_f16(acc[ch][jj][nt], (const uint32_t*)&ah[jj], bh);
                }
#pragma unroll
            for (int jj = 0; jj < NJJ; jj++) ah[jj] = ahn[jj];
        }
        __syncthreads();   // all fragment reads done before act is overwritten

        if (layer == 0) {
#pragma unroll
            for (int jj = 0; jj < NJJ; jj++)
#pragma unroll
                for (int nt = 0; nt < NT; nt++)
#pragma unroll
                    for (int r = 0; r < 4; r++) {
                        int j = (wid * NJJ + jj) * 16 + gid + ((r >> 1) << 3);
                        int p = nt * 8 + tig * 2 + (r & 1);
                        float zv = acc[0][jj][nt][r] + b2[j];
                        float y = fast_tanh(zv);
                        float g = 1.f - y * y;
                        float tg = 2.f * y * g;
                        float zd0 = acc[1][jj][nt][r];
                        float zd1 = acc[2][jj][nt][r];
                        float zd2 = acc[3][jj][nt][r];
                        float zl  = acc[4][jj][nt][r];
                        frag_store(act, 0, p, j, y);
                        frag_store(act, 1, p, j, g * zd0);
                        frag_store(act, 2, p, j, g * zd1);
                        frag_store(act, 3, p, j, g * zd2);
                        float dsq = fmaf(zd0, zd0, fmaf(zd1, zd1, zd2 * zd2));
                        frag_store(act, 4, p, j, fmaf(g, zl, -tg * dsq));
                    }
            __syncthreads();
        } else {
#pragma unroll
            for (int jj = 0; jj < NJJ; jj++)
#pragma unroll
                for (int nt = 0; nt < NT; nt++)
#pragma unroll
                    for (int r = 0; r < 4; r++) {
                        int j = (wid * NJJ + jj) * 16 + gid + ((r >> 1) << 3);
                        float w4 = W4[j];
                        float zv = acc[0][jj][nt][r] + b3[j];
                        float y = fast_tanh(zv);
                        float g = 1.f - y * y;
                        float tg = 2.f * y * g;
                        float zd0 = acc[1][jj][nt][r];
                        float zd1 = acc[2][jj][nt][r];
                        float zd2 = acc[3][jj][nt][r];
                        float zl  = acc[4][jj][nt][r];
                        float dsq = fmaf(zd0, zd0, fmaf(zd1, zd1, zd2 * zd2));
                        float lap = fmaf(g, zl, -tg * dsq);
                        us[nt][r & 1] = fmaf(y, w4, us[nt][r & 1]);
                        ls[nt][r & 1] = fmaf(lap, w4, ls[nt][r & 1]);
                    }
        }
    }

    // reduce over gid (lane bits 2..4); survivors lanes 0..3 (tig)
#pragma unroll
    for (int off = 4; off <= 16; off <<= 1)
#pragma unroll
        for (int nt = 0; nt < NT; nt++)
#pragma unroll
            for (int b0 = 0; b0 < 2; b0++) {
                us[nt][b0] += __shfl_xor_sync(0xFFFFFFFFu, us[nt][b0], off);
                ls[nt][b0] += __shfl_xor_sync(0xFFFFFFFFu, ls[nt][b0], off);
            }
    if (gid == 0) {
#pragma unroll
        for (int nt = 0; nt < NT; nt++)
#pragma unroll
            for (int b0 = 0; b0 < 2; b0++) {
                int p = nt * 8 + tig * 2 + b0;
                atomicAdd(&red[p], us[nt][b0]);
                atomicAdd(&red[16 + p], ls[nt][b0]);
            }
    }

    __syncthreads();
    if (wid == 0) {
        float rr = 0.f;
        if (lane < PTS && pt0 + lane < n) {
            float u = red[lane] + b4[0];
            float l = red[16 + lane];
            float r = l + k2 * u;
            rr = r * r;
        }
#pragma unroll
        for (int off = 16; off > 0; off >>= 1)
            rr += __shfl_xor_sync(0xFFFFFFFFu, rr, off);
        if (lane == 0) atomicAdd(&g_acc, (double)rr);
    }
}

__global__ void k_zero() { g_acc = 0.0; }
__global__ void k_fin(float* out, double inv_n) { out[0] = (float)(g_acc * inv_n); }

extern "C" void kernel_launch(void* const* d_in, const int* in_sizes, int n_in,
                              void* d_out, int out_size) {
    const float* inputs = (const float*)d_in[0];
    const float* W1 = (const float*)d_in[1];
    const float* b1 = (const float*)d_in[2];
    const float* W2 = (const float*)d_in[3];
    const float* b2 = (const float*)d_in[4];
    const float* W3 = (const float*)d_in[5];
    const float* b3 = (const float*)d_in[6];
    const float* W4 = (const float*)d_in[7];
    const float* b4 = (const float*)d_in[8];

    int n = in_sizes[0] / 3;
    const double C = 343.0;
    const double OMEGA = 2.0 * 3.14159265358979323846 * 1000.0;
    float k2 = (float)((C / OMEGA) * (C / OMEGA));

    cudaFuncSetAttribute(helm_hmma, cudaFuncAttributeMaxDynamicSharedMemorySize, SMEM_ALLOC);

    int blocks = (n + PTS - 1) / PTS;
    k_zero<<<1, 1>>>();
    prep_kernel<<<(2 * 16 * 16 * 32 + 255) / 256, 256>>>(W2, W3);
    helm_hmma<<<blocks, THREADS, SMEM_ALLOC>>>(inputs, W1, b1, b2, b3, W4, b4, n, k2);
    k_fin<<<1, 1>>>((float*)d_out, 1.0 / (double)n);
}